// round 12
// baseline (speedup 1.0000x reference)
#include <cuda_runtime.h>
#include <cuda_fp16.h>
#include <cstdint>
#include <math.h>

typedef __half fp16;

#define BB  16
#define CC  512
#define HW  1024
#define GG  32
#define CPG 16
#define EPSV 1e-5f

// ---------------------------------------------------------------------------
// Scratch
// ---------------------------------------------------------------------------
#define PL_W    ((size_t)2048*512)
#define PL_GN   ((size_t)BB*HW*512)
#define PL_Q    ((size_t)BB*HW*512)
#define PL_K    ((size_t)BB*HW*512)
#define PL_V    ((size_t)BB*CC*HW)
#define PL_ATT  ((size_t)BB*HW*HW)
#define PL_HH   ((size_t)BB*HW*512)
#define PL_S    ((size_t)BB*HW*HW)

#define OFF_WH   ((size_t)0)
#define OFF_GNH  (OFF_WH  + PL_W*2)
#define OFF_QH   (OFF_GNH + PL_GN*2)
#define OFF_KH   (OFF_QH  + PL_Q*2)
#define OFF_VH   (OFF_KH  + PL_K*2)
#define OFF_AH   (OFF_VH  + PL_V*2)
#define OFF_HHH  (OFF_AH  + PL_ATT*2)
#define OFF_S    (OFF_HHH + PL_HH*2)
#define SCRATCH_BYTES (OFF_S + PL_S*2)

__device__ __align__(256) unsigned char g_scratch[SCRATCH_BYTES];

// work-stealing counters (zero-initialized; self-reset by last CTA)
__device__ int g_ctr[8];
__device__ int g_done[8];

// ---------------------------------------------------------------------------
// PTX helpers
// ---------------------------------------------------------------------------
__device__ __forceinline__ uint32_t smem_u32(const void* p) {
    uint32_t a;
    asm("{ .reg .u64 t; cvta.to.shared.u64 t, %1; cvt.u32.u64 %0, t; }" : "=r"(a) : "l"(p));
    return a;
}
__device__ __forceinline__ void ldsm4(uint32_t* r, uint32_t addr) {
    asm volatile("ldmatrix.sync.aligned.m8n8.x4.shared.b16 {%0,%1,%2,%3}, [%4];"
                 : "=r"(r[0]), "=r"(r[1]), "=r"(r[2]), "=r"(r[3]) : "r"(addr));
}
__device__ __forceinline__ void mma16816(float* d, const uint32_t* a, const uint32_t* b) {
    asm volatile("mma.sync.aligned.m16n8k16.row.col.f32.f16.f16.f32 "
        "{%0,%1,%2,%3}, {%4,%5,%6,%7}, {%8,%9}, {%0,%1,%2,%3};"
        : "+f"(d[0]), "+f"(d[1]), "+f"(d[2]), "+f"(d[3])
        : "r"(a[0]), "r"(a[1]), "r"(a[2]), "r"(a[3]), "r"(b[0]), "r"(b[1]));
}
__device__ __forceinline__ void cpasync16(uint32_t dst, const void* src) {
    asm volatile("cp.async.cg.shared.global [%0], [%1], 16;" :: "r"(dst), "l"(src));
}
#define CP_COMMIT() asm volatile("cp.async.commit_group;" ::: "memory")
#define CP_WAIT1()  asm volatile("cp.async.wait_group 1;" ::: "memory")
#define CP_WAIT0()  asm volatile("cp.async.wait_group 0;" ::: "memory")

__device__ __forceinline__ void storeH2(fp16* ph, float v0, float v1) {
    *(half2*)ph = __halves2half2(__float2half(v0), __float2half(v1));
}

// ---------------------------------------------------------------------------
// Weight conversion
// ---------------------------------------------------------------------------
__global__ __launch_bounds__(256) void convert_w_kernel(
    const float* __restrict__ Wq, const float* __restrict__ Wk,
    const float* __restrict__ Wv, const float* __restrict__ Wo,
    fp16* __restrict__ WH)
{
    int r = blockIdx.x;
    int tid = threadIdx.x;
    const float* src = (r < 512)  ? Wq + (size_t)r * 512
                     : (r < 1024) ? Wk + (size_t)(r-512) * 512
                     : (r < 1536) ? Wv + (size_t)(r-1024) * 512
                                  : Wo + (size_t)(r-1536) * 512;
    fp16* dh = WH + (size_t)r * 512;
    for (int k = tid; k < 512; k += 256) dh[k] = __float2half(src[k]);
}

// ---------------------------------------------------------------------------
// GroupNorm + SiLU -> gn plane [b][n][512]
// ---------------------------------------------------------------------------
__global__ __launch_bounds__(256) void gn_silu_kernel(
    const float* __restrict__ x, const float* __restrict__ gamma,
    const float* __restrict__ beta, fp16* __restrict__ gnH)
{
    int bg = blockIdx.x;
    int b = bg / GG, g = bg % GG;
    const float* xp = x + ((size_t)b*CC + g*CPG) * HW;
    int tid = threadIdx.x;

    float s = 0.f, ss = 0.f;
    for (int i = tid; i < CPG*HW; i += 256) {
        float v = xp[i];
        s += v; ss += v*v;
    }
    __shared__ float sh0[256], sh1[256];
    sh0[tid] = s; sh1[tid] = ss;
    __syncthreads();
    for (int o = 128; o > 0; o >>= 1) {
        if (tid < o) { sh0[tid] += sh0[tid+o]; sh1[tid] += sh1[tid+o]; }
        __syncthreads();
    }
    const float inv_n = 1.f / (float)(CPG*HW);
    float mean = sh0[0] * inv_n;
    float var  = sh1[0] * inv_n - mean*mean;
    float rstd = rsqrtf(var + EPSV);

    float gm[CPG], bt[CPG];
    #pragma unroll
    for (int cl = 0; cl < CPG; cl++) { gm[cl] = gamma[g*CPG+cl]; bt[cl] = beta[g*CPG+cl]; }

    for (int n = tid; n < HW; n += 256) {
        fp16* dh = gnH + ((size_t)b*HW + n) * 512 + g*CPG;
        #pragma unroll
        for (int cl = 0; cl < CPG; cl += 2) {
            float v0 = (xp[cl*HW + n]     - mean) * rstd * gm[cl]   + bt[cl];
            float v1 = (xp[(cl+1)*HW + n] - mean) * rstd * gm[cl+1] + bt[cl+1];
            v0 = v0 / (1.f + __expf(-v0));
            v1 = v1 / (1.f + __expf(-v1));
            storeH2(dh + cl, v0, v1);
        }
    }
}

// ---------------------------------------------------------------------------
// Warp-per-row softmax: 8 warps/block, 1 row/warp, shfl reductions only.
// ---------------------------------------------------------------------------
__global__ __launch_bounds__(256) void softmax_kernel(
    const fp16* __restrict__ s, fp16* __restrict__ aH)
{
    int w = threadIdx.x >> 5, lane = threadIdx.x & 31;
    size_t row = (size_t)blockIdx.x * 8 + w;
    const half2* sp = (const half2*)(s + row * HW);
    half2* ap = (half2*)(aH + row * HW);

    float2 v[16];
    float m = -1e30f;
    #pragma unroll
    for (int i = 0; i < 16; i++) {
        v[i] = __half22float2(sp[i*32 + lane]);
        m = fmaxf(m, fmaxf(v[i].x, v[i].y));
    }
    #pragma unroll
    for (int o = 16; o; o >>= 1) m = fmaxf(m, __shfl_xor_sync(0xffffffffu, m, o));

    float sum = 0.f;
    #pragma unroll
    for (int i = 0; i < 16; i++) {
        v[i].x = __expf(v[i].x - m);
        v[i].y = __expf(v[i].y - m);
        sum += v[i].x + v[i].y;
    }
    #pragma unroll
    for (int o = 16; o; o >>= 1) sum += __shfl_xor_sync(0xffffffffu, sum, o);
    float inv = 1.f / sum;

    #pragma unroll
    for (int i = 0; i < 16; i++)
        ap[i*32 + lane] = __floats2half2_rn(v[i].x * inv, v[i].y * inv);
}

// ---------------------------------------------------------------------------
// HMMA GEMM, pure fp16, 128x128 CTA tile, 4 warps (2x2) of 64x64, K-chunk 64,
// 3-stage cp.async pipeline crossing tile boundaries, multistage scheduling,
// fragment double buffering, DYNAMIC TILE STEALING (grid=296, atomic queue).
// EPI: 0=QK  1=V  2=SCORES(fp16)  3=AV  4=OUT
// ---------------------------------------------------------------------------
#define KC       64
#define OPB      16384
#define STAGE_B  (2*OPB)
#define SMEM_BYTES (3*STAGE_B)
#define NPERS    296

template<int KB>
__device__ __forceinline__ void load_stage(uint32_t dst, const fp16* Ap, const fp16* Bp,
                                           int tid)
{
    #pragma unroll
    for (int it = 0; it < 8; it++) {
        int e   = it*128 + tid;
        int row = e >> 3, grp = e & 7;
        uint32_t off = (uint32_t)(row*128 + ((grp ^ (row & 7)) << 4));
        cpasync16(dst + off,       Ap + (size_t)row * KB + grp*8);
        cpasync16(dst + OPB + off, Bp + (size_t)row * KB + grp*8);
    }
}

template<int EPI, int KB>
__global__ __launch_bounds__(128, 2) void hmma_gemm(
    const fp16* __restrict__ AH, size_t aStr,
    const fp16* __restrict__ BH, size_t bStr,
    const float* __restrict__ bias, const float* __restrict__ bias2,
    const float* __restrict__ xres,
    float* __restrict__ fOut, fp16* __restrict__ oH, fp16* __restrict__ o2H,
    float scale, int ntn, int per_b, int ntiles)
{
    constexpr int nch = KB / KC;
    extern __shared__ char smem[];
    __shared__ int s_nxt;
    const uint32_t sbase = smem_u32(smem);
    const int tid  = threadIdx.x;
    const int lane = tid & 31, wid = tid >> 5;
    const int wm = wid >> 1, wn = wid & 1;

    int cur = blockIdx.x;
    if (tid == 0) s_nxt = (int)gridDim.x + atomicAdd(&g_ctr[EPI], 1);

    // ldmatrix per-thread geometry
    const int aR0 = wm*64 + (lane & 15);
    const int aGs = lane >> 4;
    const int bR0 = wn*64 + (lane & 7) + ((lane >> 4) & 1) * 8;
    const int bGs = (lane >> 3) & 1;

    float acc[4][8][4];
    #pragma unroll
    for (int i = 0; i < 4; i++)
        #pragma unroll
        for (int j = 0; j < 8; j++)
            #pragma unroll
            for (int c = 0; c < 4; c++) acc[i][j][c] = 0.f;

    uint32_t afr[2][4][4];
    uint32_t bfr[2][8][2];

    auto frag_load = [&](int bf, uint32_t ab, uint32_t bb, int g) {
        uint32_t gA = (uint32_t)(g + aGs);
        uint32_t gB = (uint32_t)(g + bGs);
        #pragma unroll
        for (int mf = 0; mf < 4; mf++) {
            int r = aR0 + mf*16;
            ldsm4(afr[bf][mf], ab + (uint32_t)(r*128) + ((gA ^ (uint32_t)(r & 7)) << 4));
        }
        #pragma unroll
        for (int p = 0; p < 4; p++) {
            int r = bR0 + p*16;
            uint32_t rr[4];
            ldsm4(rr, bb + (uint32_t)(r*128) + ((gB ^ (uint32_t)(r & 7)) << 4));
            bfr[bf][2*p][0]   = rr[0]; bfr[bf][2*p][1]   = rr[1];
            bfr[bf][2*p+1][0] = rr[2]; bfr[bf][2*p+1][1] = rr[3];
        }
    };

    auto tileA = [&](int tile) -> const fp16* {
        int bz = tile / per_b; int rem = tile - bz*per_b;
        int m0 = (rem / ntn) << 7;
        return AH + (size_t)bz*aStr + (size_t)m0 * KB;
    };
    auto tileB = [&](int tile) -> const fp16* {
        int bz = tile / per_b; int rem = tile - bz*per_b;
        int n0 = (rem - (rem / ntn)*ntn) << 7;
        return BH + (size_t)bz*bStr + (size_t)n0 * KB;
    };

    const fp16* Ac = tileA(cur);
    const fp16* Bc = tileB(cur);

    // prologue: chunks 0,1 of first tile
    load_stage<KB>(sbase,           Ac,      Bc,      tid);  CP_COMMIT();
    load_stage<KB>(sbase + STAGE_B, Ac + KC, Bc + KC, tid);  CP_COMMIT();
    int pending = 2;
    CP_WAIT1(); pending = 1;
    __syncthreads();
    int nxt = s_nxt;
    bool refresh = false;
    frag_load(0, sbase, sbase + OPB, 0);

    int stage = 0;
    #pragma unroll 1
    while (true) {
        #pragma unroll 1
        for (int t = 0; t < nch; t++) {
            if (t == 1 && refresh) { nxt = s_nxt; refresh = false; }
            const uint32_t abase = sbase + stage*STAGE_B;
            const uint32_t bbase = abase + OPB;
            int sN = stage + 1; if (sN == 3) sN = 0;
            int s2 = sN + 1;    if (s2 == 3) s2 = 0;

            #pragma unroll
            for (int step = 0; step < 4; step++) {
                int cb = step & 1, nb = cb ^ 1;
                if (step == 0) {
                    int pt = t + 2;
                    const fp16* Ap = nullptr; const fp16* Bp = nullptr;
                    if (pt < nch) { Ap = Ac + pt*KC; Bp = Bc + pt*KC; }
                    else if (nxt < ntiles) {
                        Ap = tileA(nxt) + (pt - nch)*KC;
                        Bp = tileB(nxt) + (pt - nch)*KC;
                    }
                    if (Ap) {
                        load_stage<KB>(sbase + s2*STAGE_B, Ap, Bp, tid);
                        CP_COMMIT();
                        pending++;
                    }
                }
                if (step < 3) {
                    frag_load(nb, abase, bbase, (step+1)*2);
                } else {
                    if (pending >= 2)      { CP_WAIT1(); pending = 1; }
                    else if (pending == 1) { CP_WAIT0(); pending = 0; }
                    __syncthreads();
                    if ((t + 1 < nch) || (nxt < ntiles)) {
                        uint32_t na = sbase + sN*STAGE_B;
                        frag_load(nb, na, na + OPB, 0);
                    }
                }
                #pragma unroll
                for (int mf = 0; mf < 4; mf++)
                    #pragma unroll
                    for (int nf = 0; nf < 8; nf++)
                        mma16816(acc[mf][nf], afr[cb][mf], bfr[cb][nf]);
            }
            stage = sN;
        }

        // ---------------- epilogue for tile cur ----------------
        {
            int bz = cur / per_b; int rem = cur - bz*per_b;
            int m0 = (rem / ntn) << 7;
            int n0 = (rem - (rem / ntn)*ntn) << 7;
            const int tr = lane >> 2;
            const int tc = (lane & 3) * 2;

            #pragma unroll
            for (int mf = 0; mf < 4; mf++) {
                #pragma unroll
                for (int half = 0; half < 2; half++) {
                    int r = m0 + wm*64 + mf*16 + tr + half*8;
                    #pragma unroll
                    for (int nf = 0; nf < 8; nf++) {
                        int c = n0 + wn*64 + nf*8 + tc;
                        float d0 = acc[mf][nf][half*2 + 0];
                        float d1 = acc[mf][nf][half*2 + 1];

                        if (EPI == 0) {                 // QK
                            if (c < 512) {
                                d0 += bias[c]; d1 += bias[c+1];
                                size_t idx = ((size_t)bz*HW + r) * 512 + c;
                                storeH2(oH + idx, d0, d1);
                            } else {
                                d0 += bias2[c-512]; d1 += bias2[c-511];
                                size_t idx = ((size_t)bz*HW + r) * 512 + (c - 512);
                                storeH2(o2H + idx, d0, d1);
                            }
                        } else if (EPI == 1) {          // V: D[ch][i]
                            float bb = bias[r];
                            size_t idx = ((size_t)bz*CC + r) * HW + c;
                            storeH2(oH + idx, d0+bb, d1+bb);
                        } else if (EPI == 2) {          // scores fp16, * scale
                            size_t idx = ((size_t)bz*HW + r) * HW + c;
                            storeH2(oH + idx, d0*scale, d1*scale);
                        } else if (EPI == 3) {          // AV
                            size_t idx = ((size_t)bz*HW + r) * 512 + c;
                            storeH2(oH + idx, d0, d1);
                        } else {                        // OUT: + bias + residual
                            float bb = bias[r];
                            size_t off = ((size_t)bz*CC + r) * HW + c;
                            float2 xr = *(const float2*)(xres + off);
                            *(float2*)(fOut + off) = make_float2(d0+bb+xr.x, d1+bb+xr.y);
                        }
                    }
                }
            }
            #pragma unroll
            for (int i = 0; i < 4; i++)
                #pragma unroll
                for (int j = 0; j < 8; j++)
                    #pragma unroll
                    for (int cc = 0; cc < 4; cc++) acc[i][j][cc] = 0.f;
        }

        if (nxt >= ntiles) break;
        cur = nxt;
        Ac = tileA(cur);
        Bc = tileB(cur);
        if (tid == 0) s_nxt = (int)gridDim.x + atomicAdd(&g_ctr[EPI], 1);
        nxt = ntiles;          // unknown until refresh at t==1
        refresh = true;
    }

    // self-reset counters for graph replay (last CTA)
    if (tid == 0) {
        int d = atomicAdd(&g_done[EPI], 1);
        if (d == (int)gridDim.x - 1) {
            g_ctr[EPI]  = 0;
            g_done[EPI] = 0;
            __threadfence();
        }
    }
}

// ---------------------------------------------------------------------------
extern "C" void kernel_launch(void* const* d_in, const int* in_sizes, int n_in,
                              void* d_out, int out_size)
{
    const float* x     = (const float*)d_in[0];
    const float* Wq    = (const float*)d_in[1];
    const float* bq    = (const float*)d_in[2];
    const float* Wk    = (const float*)d_in[3];
    const float* bk    = (const float*)d_in[4];
    const float* Wv    = (const float*)d_in[5];
    const float* bv    = (const float*)d_in[6];
    const float* Wo    = (const float*)d_in[7];
    const float* bo    = (const float*)d_in[8];
    const float* gamma = (const float*)d_in[9];
    const float* beta  = (const float*)d_in[10];
    float* out = (float*)d_out;

    unsigned char* base = nullptr;
    cudaGetSymbolAddress((void**)&base, g_scratch);
    fp16*  WH  = (fp16*)(base + OFF_WH);
    fp16*  gnH = (fp16*)(base + OFF_GNH);
    fp16*  qH  = (fp16*)(base + OFF_QH);
    fp16*  kH  = (fp16*)(base + OFF_KH);
    fp16*  vH  = (fp16*)(base + OFF_VH);
    fp16*  aH  = (fp16*)(base + OFF_AH);
    fp16*  hhH = (fp16*)(base + OFF_HHH);
    fp16*  sH  = (fp16*)(base + OFF_S);

    cudaFuncSetAttribute((const void*)hmma_gemm<0,512>,  cudaFuncAttributeMaxDynamicSharedMemorySize, SMEM_BYTES);
    cudaFuncSetAttribute((const void*)hmma_gemm<1,512>,  cudaFuncAttributeMaxDynamicSharedMemorySize, SMEM_BYTES);
    cudaFuncSetAttribute((const void*)hmma_gemm<2,512>,  cudaFuncAttributeMaxDynamicSharedMemorySize, SMEM_BYTES);
    cudaFuncSetAttribute((const void*)hmma_gemm<3,1024>, cudaFuncAttributeMaxDynamicSharedMemorySize, SMEM_BYTES);
    cudaFuncSetAttribute((const void*)hmma_gemm<4,512>,  cudaFuncAttributeMaxDynamicSharedMemorySize, SMEM_BYTES);

    const float scale = 1.0f / sqrtf((float)CC);
    const size_t PXS = (size_t)HW * 512;
    const size_t CHS = (size_t)CC * HW;

    convert_w_kernel<<<2048, 256>>>(Wq, Wk, Wv, Wo, WH);
    gn_silu_kernel<<<BB*GG, 256>>>(x, gamma, beta, gnH);

    // QK: M=1024 pixels (A=gn), N=1024 q|k rows (B=W), K=512. ntn=8, per_b=64.
    hmma_gemm<0,512><<<NPERS, 128, SMEM_BYTES>>>(
        gnH, PXS, WH, 0, bq, bk, nullptr, nullptr, qH, kH,
        0.f, 8, 64, 64*BB);

    // V: M=512 channels (A=Wv), N=1024 pixels (B=gn), K=512. ntn=8, per_b=32.
    hmma_gemm<1,512><<<NPERS, 128, SMEM_BYTES>>>(
        WH + (size_t)1024*512, 0, gnH, PXS, bv, nullptr, nullptr,
        nullptr, vH, nullptr, 0.f, 8, 32, 32*BB);

    // scores: M=1024 i (A=q), N=1024 j (B=k), K=512 -> fp16 * scale. per_b=64.
    hmma_gemm<2,512><<<NPERS, 128, SMEM_BYTES>>>(
        qH, PXS, kH, PXS, nullptr, nullptr, nullptr,
        nullptr, sH, nullptr, scale, 8, 64, 64*BB);

    softmax_kernel<<<BB*HW/8, 256>>>(sH, aH);

    // AV: M=1024 i (A=attn), N=512 ch (B=v), K=1024. ntn=4, per_b=32.
    hmma_gemm<3,1024><<<NPERS, 128, SMEM_BYTES>>>(
        aH, (size_t)HW*HW, vH, CHS, nullptr, nullptr, nullptr,
        nullptr, hhH, nullptr, 0.f, 4, 32, 32*BB);

    // OUT: M=512 ch (A=Wo), N=1024 i (B=hh), K=512, +bo +x. ntn=8, per_b=32.
    hmma_gemm<4,512><<<NPERS, 128, SMEM_BYTES>>>(
        WH + (size_t)1536*512, 0, hhH, PXS, bo, nullptr, x,
        out, nullptr, nullptr, 0.f, 8, 32, 32*BB);
}

// round 13
// speedup vs baseline: 1.1791x; 1.1791x over previous
#include <cuda_runtime.h>
#include <cuda_fp16.h>
#include <cstdint>
#include <math.h>

typedef __half fp16;

#define BB  16
#define CC  512
#define HW  1024
#define GG  32
#define CPG 16
#define EPSV 1e-5f

// ---------------------------------------------------------------------------
// Scratch: pure fp16 tensors; scores fp16.
// ---------------------------------------------------------------------------
#define PL_W    ((size_t)2048*512)
#define PL_GN   ((size_t)BB*HW*512)
#define PL_Q    ((size_t)BB*HW*512)
#define PL_K    ((size_t)BB*HW*512)
#define PL_V    ((size_t)BB*CC*HW)
#define PL_ATT  ((size_t)BB*HW*HW)
#define PL_HH   ((size_t)BB*HW*512)
#define PL_S    ((size_t)BB*HW*HW)

#define OFF_WH   ((size_t)0)
#define OFF_GNH  (OFF_WH  + PL_W*2)
#define OFF_QH   (OFF_GNH + PL_GN*2)
#define OFF_KH   (OFF_QH  + PL_Q*2)
#define OFF_VH   (OFF_KH  + PL_K*2)
#define OFF_AH   (OFF_VH  + PL_V*2)
#define OFF_HHH  (OFF_AH  + PL_ATT*2)
#define OFF_S    (OFF_HHH + PL_HH*2)
#define SCRATCH_BYTES (OFF_S + PL_S*2)

__device__ __align__(256) unsigned char g_scratch[SCRATCH_BYTES];

// ---------------------------------------------------------------------------
// PTX helpers
// ---------------------------------------------------------------------------
__device__ __forceinline__ uint32_t smem_u32(const void* p) {
    uint32_t a;
    asm("{ .reg .u64 t; cvta.to.shared.u64 t, %1; cvt.u32.u64 %0, t; }" : "=r"(a) : "l"(p));
    return a;
}
__device__ __forceinline__ void ldsm4(uint32_t* r, uint32_t addr) {
    asm volatile("ldmatrix.sync.aligned.m8n8.x4.shared.b16 {%0,%1,%2,%3}, [%4];"
                 : "=r"(r[0]), "=r"(r[1]), "=r"(r[2]), "=r"(r[3]) : "r"(addr));
}
__device__ __forceinline__ void mma16816(float* d, const uint32_t* a, const uint32_t* b) {
    asm volatile("mma.sync.aligned.m16n8k16.row.col.f32.f16.f16.f32 "
        "{%0,%1,%2,%3}, {%4,%5,%6,%7}, {%8,%9}, {%0,%1,%2,%3};"
        : "+f"(d[0]), "+f"(d[1]), "+f"(d[2]), "+f"(d[3])
        : "r"(a[0]), "r"(a[1]), "r"(a[2]), "r"(a[3]), "r"(b[0]), "r"(b[1]));
}
__device__ __forceinline__ void cpasync16(uint32_t dst, const void* src) {
    asm volatile("cp.async.cg.shared.global [%0], [%1], 16;" :: "r"(dst), "l"(src));
}
#define CP_COMMIT() asm volatile("cp.async.commit_group;" ::: "memory")
#define CP_WAIT1()  asm volatile("cp.async.wait_group 1;" ::: "memory")
#define CP_WAIT0()  asm volatile("cp.async.wait_group 0;" ::: "memory")

__device__ __forceinline__ void storeH2(fp16* ph, float v0, float v1) {
    *(half2*)ph = __halves2half2(__float2half(v0), __float2half(v1));
}

// ---------------------------------------------------------------------------
// Weight conversion
// ---------------------------------------------------------------------------
__global__ __launch_bounds__(256) void convert_w_kernel(
    const float* __restrict__ Wq, const float* __restrict__ Wk,
    const float* __restrict__ Wv, const float* __restrict__ Wo,
    fp16* __restrict__ WH)
{
    int r = blockIdx.x;
    int tid = threadIdx.x;
    const float* src = (r < 512)  ? Wq + (size_t)r * 512
                     : (r < 1024) ? Wk + (size_t)(r-512) * 512
                     : (r < 1536) ? Wv + (size_t)(r-1024) * 512
                                  : Wo + (size_t)(r-1536) * 512;
    fp16* dh = WH + (size_t)r * 512;
    for (int k = tid; k < 512; k += 256) dh[k] = __float2half(src[k]);
}

// ---------------------------------------------------------------------------
// GroupNorm + SiLU -> gn plane [b][n][512]
// ---------------------------------------------------------------------------
__global__ __launch_bounds__(256) void gn_silu_kernel(
    const float* __restrict__ x, const float* __restrict__ gamma,
    const float* __restrict__ beta, fp16* __restrict__ gnH)
{
    int bg = blockIdx.x;
    int b = bg / GG, g = bg % GG;
    const float* xp = x + ((size_t)b*CC + g*CPG) * HW;
    int tid = threadIdx.x;

    float s = 0.f, ss = 0.f;
    for (int i = tid; i < CPG*HW; i += 256) {
        float v = xp[i];
        s += v; ss += v*v;
    }
    __shared__ float sh0[256], sh1[256];
    sh0[tid] = s; sh1[tid] = ss;
    __syncthreads();
    for (int o = 128; o > 0; o >>= 1) {
        if (tid < o) { sh0[tid] += sh0[tid+o]; sh1[tid] += sh1[tid+o]; }
        __syncthreads();
    }
    const float inv_n = 1.f / (float)(CPG*HW);
    float mean = sh0[0] * inv_n;
    float var  = sh1[0] * inv_n - mean*mean;
    float rstd = rsqrtf(var + EPSV);

    float gm[CPG], bt[CPG];
    #pragma unroll
    for (int cl = 0; cl < CPG; cl++) { gm[cl] = gamma[g*CPG+cl]; bt[cl] = beta[g*CPG+cl]; }

    for (int n = tid; n < HW; n += 256) {
        fp16* dh = gnH + ((size_t)b*HW + n) * 512 + g*CPG;
        #pragma unroll
        for (int cl = 0; cl < CPG; cl += 2) {
            float v0 = (xp[cl*HW + n]     - mean) * rstd * gm[cl]   + bt[cl];
            float v1 = (xp[(cl+1)*HW + n] - mean) * rstd * gm[cl+1] + bt[cl+1];
            v0 = v0 / (1.f + __expf(-v0));
            v1 = v1 / (1.f + __expf(-v1));
            storeH2(dh + cl, v0, v1);
        }
    }
}

// ---------------------------------------------------------------------------
// Warp-per-row softmax: 8 warps/block, 1 row/warp, shfl reductions only.
// ---------------------------------------------------------------------------
__global__ __launch_bounds__(256) void softmax_kernel(
    const fp16* __restrict__ s, fp16* __restrict__ aH)
{
    int w = threadIdx.x >> 5, lane = threadIdx.x & 31;
    size_t row = (size_t)blockIdx.x * 8 + w;
    const half2* sp = (const half2*)(s + row * HW);
    half2* ap = (half2*)(aH + row * HW);

    float2 v[16];
    float m = -1e30f;
    #pragma unroll
    for (int i = 0; i < 16; i++) {
        v[i] = __half22float2(sp[i*32 + lane]);
        m = fmaxf(m, fmaxf(v[i].x, v[i].y));
    }
    #pragma unroll
    for (int o = 16; o; o >>= 1) m = fmaxf(m, __shfl_xor_sync(0xffffffffu, m, o));

    float sum = 0.f;
    #pragma unroll
    for (int i = 0; i < 16; i++) {
        v[i].x = __expf(v[i].x - m);
        v[i].y = __expf(v[i].y - m);
        sum += v[i].x + v[i].y;
    }
    #pragma unroll
    for (int o = 16; o; o >>= 1) sum += __shfl_xor_sync(0xffffffffu, sum, o);
    float inv = 1.f / sum;

    #pragma unroll
    for (int i = 0; i < 16; i++)
        ap[i*32 + lane] = __floats2half2_rn(v[i].x * inv, v[i].y * inv);
}

// ---------------------------------------------------------------------------
// HMMA GEMM, pure fp16. CTA 128x128, 4 warps (2x2), warp tile 64x64, K-chunk
// 64, 3-stage cp.async pipeline with cutlass-multistage scheduling:
// wait+sync at stage TAIL, next chunk's step-0 fragments prefetched right
// after the barrier -> no post-barrier ldsm bubble. Static x-major grid
// (consecutive CTAs share the A row-block in L2).
// EPI: 0=QK  1=V  2=SCORES(fp16)  3=AV  4=OUT
// ---------------------------------------------------------------------------
#define KC       64
#define OPB      16384
#define STAGE_B  (2*OPB)
#define SMEM_BYTES (3*STAGE_B)

__device__ __forceinline__ void load_stage(uint32_t dst, const fp16* Ap, const fp16* Bp,
                                           int Kb, int tid)
{
    #pragma unroll
    for (int it = 0; it < 8; it++) {
        int e   = it*128 + tid;
        int row = e >> 3, grp = e & 7;
        uint32_t off = (uint32_t)(row*128 + ((grp ^ (row & 7)) << 4));
        cpasync16(dst + off,       Ap + (size_t)row * Kb + grp*8);
        cpasync16(dst + OPB + off, Bp + (size_t)row * Kb + grp*8);
    }
}

template<int EPI>
__global__ __launch_bounds__(128, 2) void hmma_gemm(
    const fp16* __restrict__ AH, size_t aStr,
    const fp16* __restrict__ BH, size_t bStr, int Kb,
    const float* __restrict__ bias, const float* __restrict__ bias2,
    const float* __restrict__ xres,
    float* __restrict__ fOut, fp16* __restrict__ oH, fp16* __restrict__ o2H,
    float scale)
{
    extern __shared__ char smem[];
    const uint32_t sbase = smem_u32(smem);
    const int tid  = threadIdx.x;
    const int lane = tid & 31, wid = tid >> 5;
    const int wm = wid >> 1, wn = wid & 1;
    const int bz = blockIdx.z;
    const int m0 = blockIdx.y * 128, n0 = blockIdx.x * 128;

    const fp16* AHb = AH + bz*aStr + (size_t)m0 * Kb;
    const fp16* BHb = BH + bz*bStr + (size_t)n0 * Kb;

    const int nch = Kb >> 6;

    // ldmatrix per-thread geometry
    const int aR0 = wm*64 + (lane & 15);
    const int aGs = lane >> 4;
    const int bR0 = wn*64 + (lane & 7) + ((lane >> 4) & 1) * 8;
    const int bGs = (lane >> 3) & 1;

    float acc[4][8][4];
    #pragma unroll
    for (int i = 0; i < 4; i++)
        #pragma unroll
        for (int j = 0; j < 8; j++)
            #pragma unroll
            for (int c = 0; c < 4; c++) acc[i][j][c] = 0.f;

    uint32_t afr[2][4][4];
    uint32_t bfr[2][8][2];

    // fragment loader: buffer bf, stage base ab/bb, k16-group g (0,2,4,6)
    auto frag_load = [&](int bf, uint32_t ab, uint32_t bb, int g) {
        uint32_t gA = (uint32_t)(g + aGs);
        uint32_t gB = (uint32_t)(g + bGs);
        #pragma unroll
        for (int mf = 0; mf < 4; mf++) {
            int r = aR0 + mf*16;
            ldsm4(afr[bf][mf], ab + (uint32_t)(r*128) + ((gA ^ (uint32_t)(r & 7)) << 4));
        }
        #pragma unroll
        for (int p = 0; p < 4; p++) {
            int r = bR0 + p*16;
            uint32_t rr[4];
            ldsm4(rr, bb + (uint32_t)(r*128) + ((gB ^ (uint32_t)(r & 7)) << 4));
            bfr[bf][2*p][0]   = rr[0]; bfr[bf][2*p][1]   = rr[1];
            bfr[bf][2*p+1][0] = rr[2]; bfr[bf][2*p+1][1] = rr[3];
        }
    };

    // prologue: chunks 0,1 in flight; chunk0 step-0 fragments preloaded
    load_stage(sbase,           AHb,      BHb,      Kb, tid);  CP_COMMIT();
    load_stage(sbase + STAGE_B, AHb + KC, BHb + KC, Kb, tid);  CP_COMMIT();
    CP_WAIT1();
    __syncthreads();
    frag_load(0, sbase, sbase + OPB, 0);

    int stage = 0;
    #pragma unroll 1
    for (int t = 0; t < nch; t++) {
        const uint32_t abase = sbase + stage*STAGE_B;
        const uint32_t bbase = abase + OPB;
        int sN = stage + 1; if (sN == 3) sN = 0;
        int s2 = stage + 2; if (s2 >= 3) s2 -= 3;

        #pragma unroll
        for (int step = 0; step < 4; step++) {
            int cur = step & 1, nxt = cur ^ 1;
            if (step == 0 && t + 2 < nch) {
                load_stage(sbase + s2*STAGE_B, AHb + (t+2)*KC, BHb + (t+2)*KC, Kb, tid);
                CP_COMMIT();
            }
            if (step < 3) {
                frag_load(nxt, abase, bbase, (step+1)*2);
            } else {
                // stage tail: wait for chunk t+1, barrier, prefetch its step 0
                if (t + 2 < nch) CP_WAIT1(); else CP_WAIT0();
                __syncthreads();
                if (t + 1 < nch) {
                    uint32_t nab = sbase + sN*STAGE_B;
                    frag_load(nxt, nab, nab + OPB, 0);
                }
            }
            #pragma unroll
            for (int mf = 0; mf < 4; mf++)
                #pragma unroll
                for (int nf = 0; nf < 8; nf++)
                    mma16816(acc[mf][nf], afr[cur][mf], bfr[cur][nf]);
        }
        stage = sN;
    }

    // ---------------- epilogue ----------------
    const int tr = lane >> 2;
    const int tc = (lane & 3) * 2;

    #pragma unroll
    for (int mf = 0; mf < 4; mf++) {
        #pragma unroll
        for (int half = 0; half < 2; half++) {
            int r = m0 + wm*64 + mf*16 + tr + half*8;
            #pragma unroll
            for (int nf = 0; nf < 8; nf++) {
                int c = n0 + wn*64 + nf*8 + tc;
                float d0 = acc[mf][nf][half*2 + 0];
                float d1 = acc[mf][nf][half*2 + 1];

                if (EPI == 0) {                 // QK: D[i][ch], ch<512 q else k
                    if (c < 512) {
                        d0 += bias[c]; d1 += bias[c+1];
                        size_t idx = ((size_t)bz*HW + r) * 512 + c;
                        storeH2(oH + idx, d0, d1);
                    } else {
                        d0 += bias2[c-512]; d1 += bias2[c-511];
                        size_t idx = ((size_t)bz*HW + r) * 512 + (c - 512);
                        storeH2(o2H + idx, d0, d1);
                    }
                } else if (EPI == 1) {          // V: D[ch][i]
                    float bb = bias[r];
                    size_t idx = ((size_t)bz*CC + r) * HW + c;
                    storeH2(oH + idx, d0+bb, d1+bb);
                } else if (EPI == 2) {          // scores fp16, * scale
                    size_t idx = ((size_t)bz*HW + r) * HW + c;
                    storeH2(oH + idx, d0*scale, d1*scale);
                } else if (EPI == 3) {          // AV: D[i][ch]
                    size_t idx = ((size_t)bz*HW + r) * 512 + c;
                    storeH2(oH + idx, d0, d1);
                } else {                        // OUT: + bias + residual
                    float bb = bias[r];
                    size_t off = ((size_t)bz*CC + r) * HW + c;
                    float2 xr = *(const float2*)(xres + off);
                    *(float2*)(fOut + off) = make_float2(d0+bb+xr.x, d1+bb+xr.y);
                }
            }
        }
    }
}

// ---------------------------------------------------------------------------
extern "C" void kernel_launch(void* const* d_in, const int* in_sizes, int n_in,
                              void* d_out, int out_size)
{
    const float* x     = (const float*)d_in[0];
    const float* Wq    = (const float*)d_in[1];
    const float* bq    = (const float*)d_in[2];
    const float* Wk    = (const float*)d_in[3];
    const float* bk    = (const float*)d_in[4];
    const float* Wv    = (const float*)d_in[5];
    const float* bv    = (const float*)d_in[6];
    const float* Wo    = (const float*)d_in[7];
    const float* bo    = (const float*)d_in[8];
    const float* gamma = (const float*)d_in[9];
    const float* beta  = (const float*)d_in[10];
    float* out = (float*)d_out;

    unsigned char* base = nullptr;
    cudaGetSymbolAddress((void**)&base, g_scratch);
    fp16*  WH  = (fp16*)(base + OFF_WH);
    fp16*  gnH = (fp16*)(base + OFF_GNH);
    fp16*  qH  = (fp16*)(base + OFF_QH);
    fp16*  kH  = (fp16*)(base + OFF_KH);
    fp16*  vH  = (fp16*)(base + OFF_VH);
    fp16*  aH  = (fp16*)(base + OFF_AH);
    fp16*  hhH = (fp16*)(base + OFF_HHH);
    fp16*  sH  = (fp16*)(base + OFF_S);

    cudaFuncSetAttribute(hmma_gemm<0>, cudaFuncAttributeMaxDynamicSharedMemorySize, SMEM_BYTES);
    cudaFuncSetAttribute(hmma_gemm<1>, cudaFuncAttributeMaxDynamicSharedMemorySize, SMEM_BYTES);
    cudaFuncSetAttribute(hmma_gemm<2>, cudaFuncAttributeMaxDynamicSharedMemorySize, SMEM_BYTES);
    cudaFuncSetAttribute(hmma_gemm<3>, cudaFuncAttributeMaxDynamicSharedMemorySize, SMEM_BYTES);
    cudaFuncSetAttribute(hmma_gemm<4>, cudaFuncAttributeMaxDynamicSharedMemorySize, SMEM_BYTES);

    const float scale = 1.0f / sqrtf((float)CC);
    const size_t PXS = (size_t)HW * 512;
    const size_t CHS = (size_t)CC * HW;

    convert_w_kernel<<<2048, 256>>>(Wq, Wk, Wv, Wo, WH);
    gn_silu_kernel<<<BB*GG, 256>>>(x, gamma, beta, gnH);

    // QK: M=1024 pixels (A=gn), N=1024 q|k rows (B=W), K=512
    hmma_gemm<0><<<dim3(8, 8, BB), 128, SMEM_BYTES>>>(
        gnH, PXS, WH, 0, 512, bq, bk, nullptr, nullptr, qH, kH, 0.f);

    // V: M=512 channels (A=Wv), N=1024 pixels (B=gn), K=512
    hmma_gemm<1><<<dim3(8, 4, BB), 128, SMEM_BYTES>>>(
        WH + (size_t)1024*512, 0, gnH, PXS, 512,
        bv, nullptr, nullptr, nullptr, vH, nullptr, 0.f);

    // scores: M=1024 i (A=q), N=1024 j (B=k), K=512 -> fp16 * scale
    hmma_gemm<2><<<dim3(8, 8, BB), 128, SMEM_BYTES>>>(
        qH, PXS, kH, PXS, 512, nullptr, nullptr, nullptr,
        nullptr, sH, nullptr, scale);

    softmax_kernel<<<BB*HW/8, 256>>>(sH, aH);

    // AV: M=1024 i (A=attn), N=512 ch (B=v), K=1024 -> hh
    hmma_gemm<3><<<dim3(4, 8, BB), 128, SMEM_BYTES>>>(
        aH, (size_t)HW*HW, vH, CHS, 1024, nullptr, nullptr, nullptr,
        nullptr, hhH, nullptr, 0.f);

    // OUT: M=512 ch (A=Wo), N=1024 i (B=hh), K=512, +bo +x
    hmma_gemm<4><<<dim3(8, 4, BB), 128, SMEM_BYTES>>>(
        WH + (size_t)1536*512, 0, hhH, PXS, 512,
        bo, nullptr, x, out, nullptr, nullptr, 0.f);
}